// round 1
// baseline (speedup 1.0000x reference)
#include <cuda_runtime.h>
#include <cstdint>

// image2patch: x[128,1,256,256] f32 -> out[128, 126*126, 36] f32
// out[b, pr*126+pc, kr*6+kc] = x[b, 0, 2*pr+kr, 2*pc+kc]
//
// One thread per output float4 (patch = 36 floats = 9 float4, 16B-aligned).
// Stores fully coalesced; loads are small gathers that hit L1/L2 (one image
// = 256 KB). Streaming store hint keeps the write stream from thrashing L2.

namespace {
constexpr int IMG      = 256;
constexpr int NPOS     = 126;                  // positions per axis
constexpr int PATCHES  = NPOS * NPOS;          // 15876 per image
constexpr int BATCH    = 128;
constexpr long long TOTAL_FLOATS = (long long)BATCH * PATCHES * 36; // 73,156,608
constexpr int TOTAL_F4 = (int)(TOTAL_FLOATS / 4);                   // 18,289,152
}

__global__ void __launch_bounds__(256) image2patch_kernel(
    const float* __restrict__ x, float* __restrict__ out)
{
    int f = blockIdx.x * blockDim.x + threadIdx.x;
    if (f >= TOTAL_F4) return;

    int patch = f / 9;                 // which 36-float patch
    int q     = f - patch * 9;         // which float4 within the patch
    int b     = patch / PATCHES;
    int p     = patch - b * PATCHES;
    int pr    = p / NPOS;
    int pc    = p - pr * NPOS;

    const float* img = x + (size_t)b * (IMG * IMG);
    int r0 = 2 * pr;
    int c0 = 2 * pc;
    int k0 = q * 4;                    // first element index within patch (0..32)

    float4 v;
    {
        int k = k0 + 0; int kr = k / 6; int kc = k - kr * 6;
        v.x = __ldg(&img[(r0 + kr) * IMG + c0 + kc]);
    }
    {
        int k = k0 + 1; int kr = k / 6; int kc = k - kr * 6;
        v.y = __ldg(&img[(r0 + kr) * IMG + c0 + kc]);
    }
    {
        int k = k0 + 2; int kr = k / 6; int kc = k - kr * 6;
        v.z = __ldg(&img[(r0 + kr) * IMG + c0 + kc]);
    }
    {
        int k = k0 + 3; int kr = k / 6; int kc = k - kr * 6;
        v.w = __ldg(&img[(r0 + kr) * IMG + c0 + kc]);
    }

    __stcs(reinterpret_cast<float4*>(out) + f, v);   // streaming store
}

extern "C" void kernel_launch(void* const* d_in, const int* in_sizes, int n_in,
                              void* d_out, int out_size)
{
    const float* x = (const float*)d_in[0];
    float* out = (float*)d_out;

    constexpr int THREADS = 256;
    int blocks = (TOTAL_F4 + THREADS - 1) / THREADS;
    image2patch_kernel<<<blocks, THREADS>>>(x, out);
}

// round 2
// speedup vs baseline: 1.0304x; 1.0304x over previous
#include <cuda_runtime.h>
#include <cstdint>

// image2patch: x[128,1,256,256] f32 -> out[128, 126*126, 36] f32
// out[b, pr*126+pc, kr*6+kc] = x[b, 0, 2*pr+kr, 2*pc+kc]
//
// One thread per output float4 (patch = 36 floats = 9 float4s, 16B-aligned).
// Each output float4 is assembled from exactly TWO 8B-aligned float2 gathers:
//   element offsets e0=4q and e1=4q+2; their in-patch columns kc are always
//   even, and patch origin column c0=2*pc is even, so both loads are
//   float2-aligned. This halves L1 load instructions/wavefronts vs scalar.
// Stores stay perfectly coalesced (consecutive threads -> consecutive 16B),
// with a streaming hint so the 292MB write stream doesn't evict the image.

namespace {
constexpr int IMG      = 256;
constexpr int NPOS     = 126;                  // positions per axis
constexpr int PATCHES  = NPOS * NPOS;          // 15876 per image
constexpr int BATCH    = 128;
constexpr long long TOTAL_FLOATS = (long long)BATCH * PATCHES * 36; // 73,156,608
constexpr int TOTAL_F4 = (int)(TOTAL_FLOATS / 4);                   // 18,289,152
}

__global__ void __launch_bounds__(256) image2patch_kernel(
    const float2* __restrict__ x2, float4* __restrict__ out)
{
    int f = blockIdx.x * blockDim.x + threadIdx.x;
    if (f >= TOTAL_F4) return;

    int patch = f / 9;                 // which 36-float patch
    int q     = f - patch * 9;         // which float4 within the patch
    int b     = patch / PATCHES;
    int p     = patch - b * PATCHES;
    int pr    = p / NPOS;
    int pc    = p - pr * NPOS;

    // image base in float2 units (IMG/2 = 128 float2 per row)
    const float2* img2 = x2 + (size_t)b * (IMG * (IMG / 2));

    int r0 = 2 * pr;                   // top row of patch
    // element offsets within the 36-float patch for this quad
    int e0 = 4 * q;
    int e1 = e0 + 2;
    int kr0 = e0 / 6, kc0 = e0 - kr0 * 6;   // kc0 in {0,2,4}
    int kr1 = e1 / 6, kc1 = e1 - kr1 * 6;   // kc1 in {0,2,4}

    // float2-unit index: (row)*128 + pc + kc/2
    int i0 = (r0 + kr0) * (IMG / 2) + pc + (kc0 >> 1);
    int i1 = (r0 + kr1) * (IMG / 2) + pc + (kc1 >> 1);

    float2 a = __ldg(img2 + i0);
    float2 c = __ldg(img2 + i1);

    float4 v;
    v.x = a.x; v.y = a.y; v.z = c.x; v.w = c.y;

    __stcs(out + f, v);                // streaming store
}

extern "C" void kernel_launch(void* const* d_in, const int* in_sizes, int n_in,
                              void* d_out, int out_size)
{
    const float2* x2 = (const float2*)d_in[0];
    float4* out = (float4*)d_out;

    constexpr int THREADS = 256;
    int blocks = (TOTAL_F4 + THREADS - 1) / THREADS;
    image2patch_kernel<<<blocks, THREADS>>>(x2, out);
}

// round 3
// speedup vs baseline: 1.5174x; 1.4726x over previous
#include <cuda_runtime.h>
#include <cstdint>

// image2patch: x[128,1,256,256] f32 -> out[128, 126*126, 36] f32
// out[b, pr*126+pc, kr*6+kc] = x[b, 0, 2*pr+kr, 2*pc+kc]
//
// Smem-staged shuffle. One block per (b, pr) patch-row:
//   1) coalesced LDG.128 of 6 image rows (6KB) into padded smem
//   2) per-thread gather from smem (LDS pipe, cheap) into output float4s
//   3) perfectly coalesced streaming STG.128 (store side dominates: 292MB)
// Row pad = 4 floats (stride 260): keeps float4 smem stores 16B-aligned and
// shifts each row by 4 banks to break row-vs-row bank collisions.

namespace {
constexpr int IMG   = 256;
constexpr int NPOS  = 126;                // positions per axis
constexpr int ROWS  = 6;                  // patch height
constexpr int SROW  = IMG + 4;            // padded smem row stride (floats)
constexpr int F4_PER_BLOCK = NPOS * 9;    // 126 patches * 9 float4 = 1134
constexpr int THREADS = 256;
}

__global__ void __launch_bounds__(THREADS) image2patch_kernel(
    const float* __restrict__ x, float4* __restrict__ out)
{
    __shared__ float s[ROWS * SROW];

    const int pr = blockIdx.x;            // 0..125
    const int b  = blockIdx.y;            // 0..127
    const int tid = threadIdx.x;

    const float* img = x + (size_t)b * (IMG * IMG);
    const int r0 = 2 * pr;

    // --- load 6 rows x 64 float4 = 384 float4 into smem, coalesced ---
    for (int i = tid; i < ROWS * (IMG / 4); i += THREADS) {
        int r  = i >> 6;                  // i / 64
        int c4 = i & 63;                  // i % 64
        float4 v = __ldg(reinterpret_cast<const float4*>(img + (r0 + r) * IMG) + c4);
        *reinterpret_cast<float4*>(&s[r * SROW + c4 * 4]) = v;
    }
    __syncthreads();

    // --- emit 1134 output float4s, coalesced streaming stores ---
    float4* outBase = out + ((size_t)b * NPOS + pr) * F4_PER_BLOCK;

    #pragma unroll
    for (int it = 0; it < 5; ++it) {
        int f = tid + it * THREADS;
        if (f >= F4_PER_BLOCK) break;

        int pc = f / 9;
        int q  = f - pc * 9;
        int e0 = 4 * q;                   // element offsets within patch
        int e1 = e0 + 2;
        int kr0 = e0 / 6, kc0 = e0 - kr0 * 6;   // kc in {0,2,4}
        int kr1 = e1 / 6, kc1 = e1 - kr1 * 6;

        float2 a = *reinterpret_cast<const float2*>(&s[kr0 * SROW + 2 * pc + kc0]);
        float2 c = *reinterpret_cast<const float2*>(&s[kr1 * SROW + 2 * pc + kc1]);

        float4 v;
        v.x = a.x; v.y = a.y; v.z = c.x; v.w = c.y;
        __stcs(outBase + f, v);
    }
}

extern "C" void kernel_launch(void* const* d_in, const int* in_sizes, int n_in,
                              void* d_out, int out_size)
{
    const float* x = (const float*)d_in[0];
    float4* out = (float4*)d_out;

    dim3 grid(NPOS, 128);                 // (pr, b)
    image2patch_kernel<<<grid, THREADS>>>(x, out);
}

// round 4
// speedup vs baseline: 1.5522x; 1.0229x over previous
#include <cuda_runtime.h>
#include <cstdint>

// image2patch: x[128,1,256,256] f32 -> out[128, 126*126, 36] f32
// out[b, pr*126+pc, kr*6+kc] = x[b, 0, 2*pr+kr, 2*pc+kc]
//
// Smem-staged shuffle, 3 patch-rows per block (126 = 3*42):
//   block (j, b) covers pr = 3j..3j+2, which needs image rows 6j..6j+9
//   (10 rows instead of 18 -> 44% less LDG/STS than 1 patch-row/block).
//   1) coalesced LDG.128 of 10 rows (10KB) into padded smem
//   2) per-thread float2 gathers from smem (LDS pipe)
//   3) 3402 perfectly coalesced streaming STG.128 per block (contiguous
//      output segment -> store side, 292MB total, stays at peak efficiency)

namespace {
constexpr int IMG   = 256;
constexpr int NPOS  = 126;                 // positions per axis
constexpr int PROWS = 3;                   // patch-rows per block
constexpr int SROWS = 2 * PROWS + 4;       // 10 image rows staged
constexpr int SROW  = IMG + 4;             // padded smem row stride (floats)
constexpr int F4_PER_PROW  = NPOS * 9;     // 1134
constexpr int F4_PER_BLOCK = PROWS * F4_PER_PROW;  // 3402
constexpr int THREADS = 256;
}

__global__ void __launch_bounds__(THREADS) image2patch_kernel(
    const float* __restrict__ x, float4* __restrict__ out)
{
    __shared__ float s[SROWS * SROW];

    const int j  = blockIdx.x;             // 0..41  (patch-row triple)
    const int b  = blockIdx.y;             // 0..127
    const int tid = threadIdx.x;

    const float* img = x + (size_t)b * (IMG * IMG);
    const int r0 = 6 * j;                  // first image row needed

    // --- load 10 rows x 64 float4 = 640 float4 into smem, coalesced ---
    #pragma unroll
    for (int it = 0; it < 3; ++it) {
        int i = tid + it * THREADS;
        if (i < SROWS * (IMG / 4)) {
            int r  = i >> 6;               // i / 64
            int c4 = i & 63;               // i % 64
            float4 v = __ldg(reinterpret_cast<const float4*>(img + (r0 + r) * IMG) + c4);
            *reinterpret_cast<float4*>(&s[r * SROW + c4 * 4]) = v;
        }
    }
    __syncthreads();

    // --- emit 3402 output float4s, contiguous + coalesced streaming stores ---
    float4* outBase = out + ((size_t)b * NPOS + 3 * j) * F4_PER_PROW;

    #pragma unroll
    for (int it = 0; it < 14; ++it) {
        int f = tid + it * THREADS;
        if (f >= F4_PER_BLOCK) break;

        int pj = f / 9;                    // 0..377: local patch index
        int q  = f - pj * 9;               // float4 within patch
        int prl = pj / NPOS;               // 0..2: local patch-row
        int pc  = pj - prl * NPOS;         // 0..125

        int e0 = 4 * q;                    // element offsets within patch
        int e1 = e0 + 2;
        int kr0 = e0 / 6, kc0 = e0 - kr0 * 6;   // kc in {0,2,4}
        int kr1 = e1 / 6, kc1 = e1 - kr1 * 6;

        int rbase = 2 * prl;
        float2 a = *reinterpret_cast<const float2*>(&s[(rbase + kr0) * SROW + 2 * pc + kc0]);
        float2 c = *reinterpret_cast<const float2*>(&s[(rbase + kr1) * SROW + 2 * pc + kc1]);

        float4 v;
        v.x = a.x; v.y = a.y; v.z = c.x; v.w = c.y;
        __stcs(outBase + f, v);
    }
}

extern "C" void kernel_launch(void* const* d_in, const int* in_sizes, int n_in,
                              void* d_out, int out_size)
{
    const float* x = (const float*)d_in[0];
    float4* out = (float4*)d_out;

    dim3 grid(NPOS / PROWS, 128);          // (42, 128)
    image2patch_kernel<<<grid, THREADS>>>(x, out);
}

// round 5
// speedup vs baseline: 1.5702x; 1.0116x over previous
#include <cuda_runtime.h>
#include <cstdint>

// image2patch: x[128,1,256,256] f32 -> out[128, 126*126, 36] f32
// out[b, pr*126+pc, kr*6+kc] = x[b, 0, 2*pr+kr, 2*pc+kc]
//
// Smem-staged shuffle, 6 patch-rows per block (126 = 6*21), 512 threads:
//   1) coalesced LDG.128 of 16 image rows (16KB) into padded smem (2 iters)
//   2) emit with fixed-role threads: q = tid%9 is loop-invariant, so the
//      within-patch (kr,kc) decomposition is computed ONCE per thread;
//      per-iteration work = one /126 + 2 LDS.64 + 1 coalesced STG.128
//   3) stores remain perfectly coalesced + streaming (f = tid + 504*it)

namespace {
constexpr int IMG   = 256;
constexpr int NPOS  = 126;                   // positions per axis
constexpr int PROWS = 6;                     // patch-rows per block
constexpr int SROWS = 2 * (PROWS - 1) + 6;   // 16 image rows staged
constexpr int SROW  = IMG + 4;               // padded smem row stride (floats)
constexpr int PATCH_PER_BLOCK = PROWS * NPOS;            // 756
constexpr int F4_PER_BLOCK    = PATCH_PER_BLOCK * 9;     // 6804
constexpr int THREADS = 512;
constexpr int ACTIVE  = 504;                 // 56 patches * 9 quads per iter
}

__global__ void __launch_bounds__(THREADS) image2patch_kernel(
    const float* __restrict__ x, float4* __restrict__ out)
{
    __shared__ float s[SROWS * SROW];

    const int j   = blockIdx.x;              // 0..20  (patch-row sextet)
    const int b   = blockIdx.y;              // 0..127
    const int tid = threadIdx.x;

    const float* img = x + (size_t)b * (IMG * IMG);
    const int r0 = 12 * j;                   // first image row needed

    // --- load 16 rows x 64 float4 = 1024 float4 into smem, coalesced ---
    #pragma unroll
    for (int it = 0; it < 2; ++it) {
        int i  = tid + it * THREADS;         // 0..1023, exact
        int r  = i >> 6;                     // i / 64
        int c4 = i & 63;                     // i % 64
        float4 v = __ldg(reinterpret_cast<const float4*>(img + (r0 + r) * IMG) + c4);
        *reinterpret_cast<float4*>(&s[r * SROW + c4 * 4]) = v;
    }
    __syncthreads();

    if (tid >= ACTIVE) return;

    // --- loop-invariant per-thread decomposition ---
    const int q   = tid % 9;                 // float4 index within patch
    const int pj0 = tid / 9;                 // starting local patch index
    const int e0  = 4 * q;
    const int e1  = e0 + 2;
    const int kr0 = e0 / 6, kc0 = e0 - kr0 * 6;   // kc in {0,2,4}
    const int kr1 = e1 / 6, kc1 = e1 - kr1 * 6;

    float4* outPtr = out + ((size_t)b * NPOS + PROWS * j) * (NPOS * 9) + tid;

    #pragma unroll
    for (int it = 0; it < 14; ++it) {
        int pj = pj0 + 56 * it;              // local patch index
        if (pj >= PATCH_PER_BLOCK) break;

        int prl = pj / NPOS;                 // 0..5
        int pc  = pj - prl * NPOS;           // 0..125
        int rb  = 2 * prl;
        int cb  = 2 * pc;

        float2 a = *reinterpret_cast<const float2*>(&s[(rb + kr0) * SROW + cb + kc0]);
        float2 c = *reinterpret_cast<const float2*>(&s[(rb + kr1) * SROW + cb + kc1]);

        float4 v;
        v.x = a.x; v.y = a.y; v.z = c.x; v.w = c.y;
        __stcs(outPtr + (size_t)it * ACTIVE, v);
    }
}

extern "C" void kernel_launch(void* const* d_in, const int* in_sizes, int n_in,
                              void* d_out, int out_size)
{
    const float* x = (const float*)d_in[0];
    float4* out = (float4*)d_out;

    dim3 grid(NPOS / PROWS, 128);            // (21, 128)
    image2patch_kernel<<<grid, THREADS>>>(x, out);
}